// round 1
// baseline (speedup 1.0000x reference)
#include <cuda_runtime.h>
#include <cstdint>

// Problem constants
#define MB   8192      // batch rows (M)
#define NB   4096      // 4*H (N)
#define KB   2048      // In + H (K, logical concat)
#define HD   1024

// GEMM tiling
#define BM   128
#define BN   128
#define BK   16
#define LDT  20        // padded smem row stride (floats) -> conflict-free + 16B aligned
#define TILE_U32 (128*LDT)            // 2560 u32 per tile
#define STAGE_U32 (2*TILE_U32)        // A+B per stage

// 134 MB scratch for the pre-activation gates v = x@w_ih^T + h@w_hh^T
__device__ float g_v[(size_t)MB * NB];

__device__ __forceinline__ uint32_t f2tf(float f) {
    uint32_t u;
    asm("cvt.rna.tf32.f32 %0, %1;" : "=r"(u) : "f"(f));
    return u;
}

__device__ __forceinline__ void mma_tf32(float* d, const uint32_t* a, const uint32_t* b) {
    asm volatile(
        "mma.sync.aligned.m16n8k8.row.col.f32.tf32.tf32.f32 "
        "{%0,%1,%2,%3}, {%4,%5,%6,%7}, {%8,%9}, {%0,%1,%2,%3};"
        : "+f"(d[0]), "+f"(d[1]), "+f"(d[2]), "+f"(d[3])
        : "r"(a[0]), "r"(a[1]), "r"(a[2]), "r"(a[3]), "r"(b[0]), "r"(b[1]));
}

// v[M,N] = x[M,1024] @ w_ih[N,1024]^T + h[M,1024] @ w_hh[N,1024]^T
// TN GEMM, K contiguous on both sides. K tiles 0..63 come from (x,w_ih),
// tiles 64..127 from (h,w_hh).
__global__ __launch_bounds__(256, 2)
void gemm_tf32_kernel(const float* __restrict__ x, const float* __restrict__ h,
                      const float* __restrict__ w_ih, const float* __restrict__ w_hh)
{
    __shared__ uint32_t sm[2 * STAGE_U32];   // 40 KB: 2 stages x (A tile + B tile)

    const int tid  = threadIdx.x;
    const int bm   = blockIdx.y * BM;
    const int bn   = blockIdx.x * BN;
    const int warp = tid >> 5, lane = tid & 31;
    const int wm   = (warp & 1) * 64;        // warp M offset (2 rows of warps)
    const int wn   = (warp >> 1) * 32;       // warp N offset (4 cols of warps)
    const int quad = lane >> 2, tq = lane & 3;

    // global-load mapping: each thread moves 2 float4 of A and 2 of B per tile
    const int lrow = tid >> 2;               // 0..63
    const int lc4  = (tid & 3) * 4;          // 0,4,8,12

    float acc[4][4][4];
    #pragma unroll
    for (int i = 0; i < 4; i++)
        #pragma unroll
        for (int j = 0; j < 4; j++)
            #pragma unroll
            for (int k = 0; k < 4; k++) acc[i][j][k] = 0.f;

    uint4 pa[2], pb[2];

    auto loadg = [&](int t) {
        const float *As, *Bs;
        int kk;
        if (t < 64) { As = x; Bs = w_ih; kk = t * BK; }
        else        { As = h; Bs = w_hh; kk = t * BK - 1024; }
        #pragma unroll
        for (int i = 0; i < 2; i++) {
            const int r = lrow + i * 64;
            float4 fa = *reinterpret_cast<const float4*>(As + (size_t)(bm + r) * 1024 + kk + lc4);
            float4 fb = *reinterpret_cast<const float4*>(Bs + (size_t)(bn + r) * 1024 + kk + lc4);
            pa[i] = make_uint4(f2tf(fa.x), f2tf(fa.y), f2tf(fa.z), f2tf(fa.w));
            pb[i] = make_uint4(f2tf(fb.x), f2tf(fb.y), f2tf(fb.z), f2tf(fb.w));
        }
    };
    auto stores = [&](int s) {
        uint32_t* A = sm + s * STAGE_U32;
        uint32_t* B = A + TILE_U32;
        #pragma unroll
        for (int i = 0; i < 2; i++) {
            const int r = lrow + i * 64;
            *reinterpret_cast<uint4*>(A + r * LDT + lc4) = pa[i];
            *reinterpret_cast<uint4*>(B + r * LDT + lc4) = pb[i];
        }
    };

    loadg(0);
    stores(0);
    __syncthreads();

    const int T = KB / BK;   // 128
    for (int t = 0; t < T; t++) {
        const int s = t & 1;
        if (t + 1 < T) loadg(t + 1);    // overlap global loads with MMAs

        const uint32_t* A = sm + s * STAGE_U32;
        const uint32_t* B = A + TILE_U32;

        #pragma unroll
        for (int ks = 0; ks < 2; ks++) {
            const int kb = ks * 8;
            uint32_t af[4][4], bf[4][2];
            #pragma unroll
            for (int mt = 0; mt < 4; mt++) {
                const int base = (wm + mt * 16 + quad) * LDT + kb + tq;
                af[mt][0] = A[base];
                af[mt][1] = A[base + 8 * LDT];       // row +8
                af[mt][2] = A[base + 4];             // col +4
                af[mt][3] = A[base + 8 * LDT + 4];
            }
            #pragma unroll
            for (int nt = 0; nt < 4; nt++) {
                const int base = (wn + nt * 8 + quad) * LDT + kb + tq;
                bf[nt][0] = B[base];
                bf[nt][1] = B[base + 4];
            }
            #pragma unroll
            for (int mt = 0; mt < 4; mt++)
                #pragma unroll
                for (int nt = 0; nt < 4; nt++)
                    mma_tf32(acc[mt][nt], af[mt], bf[nt]);
        }

        if (t + 1 < T) stores(s ^ 1);   // fill the other stage (safe: others read stage s)
        __syncthreads();
    }

    // Epilogue: acc -> g_v   (c0,c1 at row g; c2,c3 at row g+8; cols 2*tq, 2*tq+1)
    #pragma unroll
    for (int mt = 0; mt < 4; mt++) {
        #pragma unroll
        for (int nt = 0; nt < 4; nt++) {
            const int rg = bm + wm + mt * 16 + quad;
            const int cg = bn + wn + nt * 8 + tq * 2;
            float2 lo = make_float2(acc[mt][nt][0], acc[mt][nt][1]);
            float2 hi = make_float2(acc[mt][nt][2], acc[mt][nt][3]);
            *reinterpret_cast<float2*>(&g_v[(size_t)rg * NB + cg])        = lo;
            *reinterpret_cast<float2*>(&g_v[(size_t)(rg + 8) * NB + cg])  = hi;
        }
    }
}

__device__ __forceinline__ float sigmoidf_(float v) { return 1.f / (1.f + expf(-v)); }

// One block per batch row: 4 gate LayerNorms + gate math + cell LayerNorm + outputs.
// LN semantics (match jax ref exactly): std with ddof=1, y = gamma*(x-mean)/(std+EPS)+beta
__global__ __launch_bounds__(256)
void ln_lstm_kernel(const float* __restrict__ cprev,
                    const float* __restrict__ b_ih,
                    const float* __restrict__ gamma_ifgo, const float* __restrict__ beta_ifgo,
                    const float* __restrict__ gamma_c,    const float* __restrict__ beta_c,
                    float* __restrict__ out_h, float* __restrict__ out_c)
{
    const float EPS = 1e-6f;
    const int b   = blockIdx.x;
    const int tid = threadIdx.x;
    const int warp = tid >> 5, lane = tid & 31;
    const float* vb = g_v + (size_t)b * NB;

    float val[4][4];
    float s[4] = {0.f, 0.f, 0.f, 0.f}, q[4] = {0.f, 0.f, 0.f, 0.f};

    #pragma unroll
    for (int g = 0; g < 4; g++)
        #pragma unroll
        for (int e = 0; e < 4; e++) {
            const int j = tid + e * 256;
            float t = vb[g * HD + j] + b_ih[g * HD + j];
            val[g][e] = t;
            s[g] += t;
            q[g] += t * t;
        }

    __shared__ float red[8][8];
    __shared__ float mean_s[4], inv_s[4];

    #pragma unroll
    for (int g = 0; g < 4; g++)
        #pragma unroll
        for (int off = 16; off; off >>= 1) {
            s[g] += __shfl_xor_sync(0xffffffffu, s[g], off);
            q[g] += __shfl_xor_sync(0xffffffffu, q[g], off);
        }
    if (lane == 0) {
        #pragma unroll
        for (int g = 0; g < 4; g++) { red[warp][g] = s[g]; red[warp][g + 4] = q[g]; }
    }
    __syncthreads();
    if (tid < 4) {
        float ts = 0.f, tq2 = 0.f;
        #pragma unroll
        for (int w = 0; w < 8; w++) { ts += red[w][tid]; tq2 += red[w][tid + 4]; }
        float mean = ts * (1.f / HD);
        float var  = (tq2 - (float)HD * mean * mean) * (1.f / (HD - 1));
        var = fmaxf(var, 0.f);
        mean_s[tid] = mean;
        inv_s[tid]  = 1.f / (sqrtf(var) + EPS);
    }
    __syncthreads();

    const float m0 = mean_s[0], m1 = mean_s[1], m2 = mean_s[2], m3 = mean_s[3];
    const float i0 = inv_s[0],  i1 = inv_s[1],  i2 = inv_s[2],  i3 = inv_s[3];

    float nc[4], ogate[4];
    float cs = 0.f, cq = 0.f;
    #pragma unroll
    for (int e = 0; e < 4; e++) {
        const int j = tid + e * 256;
        float ig = (val[0][e] - m0) * i0 * gamma_ifgo[j]          + beta_ifgo[j];
        float fg = (val[1][e] - m1) * i1 * gamma_ifgo[HD + j]     + beta_ifgo[HD + j] + 1.0f;
        float gg = (val[2][e] - m2) * i2 * gamma_ifgo[2 * HD + j] + beta_ifgo[2 * HD + j];
        float og = (val[3][e] - m3) * i3 * gamma_ifgo[3 * HD + j] + beta_ifgo[3 * HD + j];
        float ncr = cprev[(size_t)b * HD + j] * sigmoidf_(fg) + sigmoidf_(ig) * tanhf(gg);
        nc[e] = ncr;
        ogate[e] = og;
        cs += ncr;
        cq += ncr * ncr;
    }

    // second reduction for cell LN
    #pragma unroll
    for (int off = 16; off; off >>= 1) {
        cs += __shfl_xor_sync(0xffffffffu, cs, off);
        cq += __shfl_xor_sync(0xffffffffu, cq, off);
    }
    __syncthreads();   // red[] reuse
    if (lane == 0) { red[warp][0] = cs; red[warp][1] = cq; }
    __syncthreads();
    __shared__ float meanc_s, invc_s;
    if (tid == 0) {
        float ts = 0.f, tq2 = 0.f;
        #pragma unroll
        for (int w = 0; w < 8; w++) { ts += red[w][0]; tq2 += red[w][1]; }
        float mean = ts * (1.f / HD);
        float var  = (tq2 - (float)HD * mean * mean) * (1.f / (HD - 1));
        var = fmaxf(var, 0.f);
        meanc_s = mean;
        invc_s  = 1.f / (sqrtf(var) + EPS);
    }
    __syncthreads();
    const float mc = meanc_s, ic = invc_s;

    #pragma unroll
    for (int e = 0; e < 4; e++) {
        const int j = tid + e * 256;
        float ncn = (nc[e] - mc) * ic * gamma_c[j] + beta_c[j];
        out_c[(size_t)b * HD + j] = ncn;
        out_h[(size_t)b * HD + j] = tanhf(ncn) * sigmoidf_(ogate[e]);
    }
}

extern "C" void kernel_launch(void* const* d_in, const int* in_sizes, int n_in,
                              void* d_out, int out_size)
{
    const float* x          = (const float*)d_in[0];
    const float* h          = (const float*)d_in[1];
    const float* c          = (const float*)d_in[2];
    const float* w_ih       = (const float*)d_in[3];
    const float* b_ih       = (const float*)d_in[4];
    const float* w_hh       = (const float*)d_in[5];
    const float* gamma_ifgo = (const float*)d_in[6];
    const float* beta_ifgo  = (const float*)d_in[7];
    const float* gamma_c    = (const float*)d_in[8];
    const float* beta_c     = (const float*)d_in[9];

    float* out_h = (float*)d_out;                       // new_h first
    float* out_c = out_h + (size_t)MB * HD;             // then new_c

    dim3 ggrid(NB / BN, MB / BM);                       // 32 x 64
    gemm_tf32_kernel<<<ggrid, 256>>>(x, h, w_ih, w_hh);
    ln_lstm_kernel<<<MB, 256>>>(c, b_ih, gamma_ifgo, beta_ifgo, gamma_c, beta_c, out_h, out_c);
}

// round 3
// speedup vs baseline: 1.5278x; 1.5278x over previous
#include <cuda_runtime.h>
#include <cstdint>

// Problem constants
#define MB   8192      // batch rows (M)
#define NB   4096      // 4*H (N)
#define KB   2048      // In + H (K, logical concat)
#define HD   1024

// GEMM tiling (legacy mma.sync tf32 + ldmatrix + cp.async)
#define BM   128
#define BN   256
#define BK   32        // 32 fp32 = 128 bytes per SMEM row (SW128 atom)
#define STAGES 4

#define A_BYTES     (BM * 128)                 // 16384
#define B_BYTES     (BN * 128)                 // 32768
#define STAGE_BYTES (A_BYTES + B_BYTES)        // 49152
#define SMEM_TOTAL  (STAGES * STAGE_BYTES)     // 196608

// 134 MB scratch for v = x@w_ih^T + h@w_hh^T
__device__ float g_v[(size_t)MB * NB];

// ---------------- helpers ----------------
__device__ __forceinline__ uint32_t smem_u32(const void* p) {
    uint32_t a;
    asm("{ .reg .u64 t; cvta.to.shared.u64 t, %1; cvt.u32.u64 %0, t; }" : "=r"(a) : "l"(p));
    return a;
}
__device__ __forceinline__ void cp16(uint32_t dst, const void* src) {
    asm volatile("cp.async.cg.shared.global [%0], [%1], 16;" :: "r"(dst), "l"(src));
}
#define CP_COMMIT() asm volatile("cp.async.commit_group;" ::: "memory")
#define CP_WAIT2()  asm volatile("cp.async.wait_group 2;" ::: "memory")

__device__ __forceinline__ void ldsm4(uint32_t* r, uint32_t a) {
    asm volatile("ldmatrix.sync.aligned.m8n8.x4.shared.b16 {%0,%1,%2,%3}, [%4];"
        : "=r"(r[0]), "=r"(r[1]), "=r"(r[2]), "=r"(r[3]) : "r"(a));
}
__device__ __forceinline__ void mma_tf32(float* d, const uint32_t* a, const uint32_t* b) {
    asm volatile(
        "mma.sync.aligned.m16n8k8.row.col.f32.tf32.tf32.f32 "
        "{%0,%1,%2,%3}, {%4,%5,%6,%7}, {%8,%9}, {%0,%1,%2,%3};"
        : "+f"(d[0]), "+f"(d[1]), "+f"(d[2]), "+f"(d[3])
        : "r"(a[0]), "r"(a[1]), "r"(a[2]), "r"(a[3]), "r"(b[0]), "r"(b[1]));
}
// SW128 swizzle on byte offset (row*128 + chunk*16)
__device__ __forceinline__ uint32_t swz(uint32_t o) { return o ^ ((o >> 3) & 0x70); }

// ---------------- GEMM ----------------
// grid (NB/BN=16, MB/BM=64), 256 threads = 8 warps, warp tile 64x64 (2x4 warp grid)
__global__ void __launch_bounds__(256, 1)
gemm_tf32_kernel(const float* __restrict__ x, const float* __restrict__ h,
                 const float* __restrict__ w_ih, const float* __restrict__ w_hh)
{
    extern __shared__ char smem[];
    const uint32_t sb = smem_u32(smem);
    const int tid = threadIdx.x, warp = tid >> 5, lane = tid & 31;
    const int bm = blockIdx.y * BM;
    const int bn = blockIdx.x * BN;
    const int wm = (warp & 1) * 64;
    const int wn = (warp >> 1) * 64;
    const int g  = lane >> 3, L = lane & 7;     // ldmatrix lane-group / row-in-group

    // issue one stage of cp.async loads (tile t -> slot t&3)
    auto issue = [&](int t) {
        const int s = t & 3;
        const float *As, *Bs;
        int kk;
        if (t < 32) { As = x; Bs = w_ih; kk = t * 32; }
        else        { As = h; Bs = w_hh; kk = t * 32 - 1024; }
        const uint32_t abase = sb + s * STAGE_BYTES;
        const uint32_t bbase = abase + A_BYTES;
        #pragma unroll
        for (int i = 0; i < 4; i++) {           // A: 128 rows x 8 chunks
            const int id = tid + 256 * i, r = id >> 3, c = id & 7;
            cp16(abase + swz((uint32_t)(r * 128 + c * 16)),
                 As + (size_t)(bm + r) * 1024 + kk + c * 4);
        }
        #pragma unroll
        for (int i = 0; i < 8; i++) {           // B: 256 rows x 8 chunks
            const int id = tid + 256 * i, r = id >> 3, c = id & 7;
            cp16(bbase + swz((uint32_t)(r * 128 + c * 16)),
                 Bs + (size_t)(bn + r) * 1024 + kk + c * 4);
        }
    };

    float acc[4][8][4];
    #pragma unroll
    for (int i = 0; i < 4; i++)
        #pragma unroll
        for (int j = 0; j < 8; j++)
            #pragma unroll
            for (int k = 0; k < 4; k++) acc[i][j][k] = 0.f;

    issue(0); CP_COMMIT();
    issue(1); CP_COMMIT();
    issue(2); CP_COMMIT();

    const int T = KB / BK;   // 64
    for (int t = 0; t < T; t++) {
        const int s = t & 3;
        CP_WAIT2();
        __syncthreads();
        const uint32_t abase = sb + s * STAGE_BYTES;
        const uint32_t bbase = abase + A_BYTES;

        #pragma unroll
        for (int ks = 0; ks < 4; ks++) {        // 4 x k8 per BK=32
            uint32_t af[4][4], bf[4][4];
            // A fragments: mat g: rows wm+mt*16+(g&1)*8+L, chunk 2ks+(g>>1)
            #pragma unroll
            for (int mt = 0; mt < 4; mt++) {
                const int row = wm + mt * 16 + (g & 1) * 8 + L;
                const int ch  = 2 * ks + (g >> 1);
                ldsm4(af[mt], abase + swz((uint32_t)(row * 128 + ch * 16)));
            }
            // B fragments (2 n-tiles per ldmatrix.x4):
            // mat g: rows wn+p*16+(g>>1)*8+L, chunk 2ks+(g&1)
            #pragma unroll
            for (int p = 0; p < 4; p++) {
                const int row = wn + p * 16 + (g >> 1) * 8 + L;
                const int ch  = 2 * ks + (g & 1);
                ldsm4(bf[p], bbase + swz((uint32_t)(row * 128 + ch * 16)));
            }
            #pragma unroll
            for (int mt = 0; mt < 4; mt++)
                #pragma unroll
                for (int p = 0; p < 4; p++) {
                    mma_tf32(acc[mt][2 * p],     af[mt], &bf[p][0]);
                    mma_tf32(acc[mt][2 * p + 1], af[mt], &bf[p][2]);
                }
        }
        __syncthreads();
        if (t + 3 < T) issue(t + 3);
        CP_COMMIT();    // unconditional: keeps wait_group accounting exact
    }

    // epilogue: thread (q,tq): c0,c1 at (row+q, col+2tq), c2,c3 at row+q+8
    const int q = lane >> 2, tq = lane & 3;
    #pragma unroll
    for (int mt = 0; mt < 4; mt++) {
        const int rg = bm + wm + mt * 16 + q;
        #pragma unroll
        for (int nt = 0; nt < 8; nt++) {
            const int cg = bn + wn + nt * 8 + 2 * tq;
            *reinterpret_cast<float2*>(&g_v[(size_t)rg * NB + cg]) =
                make_float2(acc[mt][nt][0], acc[mt][nt][1]);
            *reinterpret_cast<float2*>(&g_v[(size_t)(rg + 8) * NB + cg]) =
                make_float2(acc[mt][nt][2], acc[mt][nt][3]);
        }
    }
}

// ---------------- LayerNorm-LSTM pointwise kernel ----------------
__device__ __forceinline__ float sigmoidf_(float v) { return 1.f / (1.f + expf(-v)); }

__global__ __launch_bounds__(256)
void ln_lstm_kernel(const float* __restrict__ cprev,
                    const float* __restrict__ b_ih,
                    const float* __restrict__ gamma_ifgo, const float* __restrict__ beta_ifgo,
                    const float* __restrict__ gamma_c,    const float* __restrict__ beta_c,
                    float* __restrict__ out_h, float* __restrict__ out_c)
{
    const float EPS = 1e-6f;
    const int b   = blockIdx.x;
    const int tid = threadIdx.x;
    const int warp = tid >> 5, lane = tid & 31;
    const float* vb = g_v + (size_t)b * NB;

    float val[4][4];
    float s[4] = {0.f, 0.f, 0.f, 0.f}, q[4] = {0.f, 0.f, 0.f, 0.f};

    #pragma unroll
    for (int g = 0; g < 4; g++)
        #pragma unroll
        for (int e = 0; e < 4; e++) {
            const int j = tid + e * 256;
            float t = vb[g * HD + j] + b_ih[g * HD + j];
            val[g][e] = t;
            s[g] += t;
            q[g] += t * t;
        }

    __shared__ float red[8][8];
    __shared__ float mean_s[4], inv_s[4];

    #pragma unroll
    for (int g = 0; g < 4; g++)
        #pragma unroll
        for (int off = 16; off; off >>= 1) {
            s[g] += __shfl_xor_sync(0xffffffffu, s[g], off);
            q[g] += __shfl_xor_sync(0xffffffffu, q[g], off);
        }
    if (lane == 0) {
        #pragma unroll
        for (int g = 0; g < 4; g++) { red[warp][g] = s[g]; red[warp][g + 4] = q[g]; }
    }
    __syncthreads();
    if (tid < 4) {
        float ts = 0.f, tq2 = 0.f;
        #pragma unroll
        for (int w = 0; w < 8; w++) { ts += red[w][tid]; tq2 += red[w][tid + 4]; }
        float mean = ts * (1.f / HD);
        float var  = (tq2 - (float)HD * mean * mean) * (1.f / (HD - 1));
        var = fmaxf(var, 0.f);
        mean_s[tid] = mean;
        inv_s[tid]  = 1.f / (sqrtf(var) + EPS);
    }
    __syncthreads();

    const float m0 = mean_s[0], m1 = mean_s[1], m2 = mean_s[2], m3 = mean_s[3];
    const float i0 = inv_s[0],  i1 = inv_s[1],  i2 = inv_s[2],  i3 = inv_s[3];

    float nc[4], ogate[4];
    float cs = 0.f, cq = 0.f;
    #pragma unroll
    for (int e = 0; e < 4; e++) {
        const int j = tid + e * 256;
        float ig = (val[0][e] - m0) * i0 * gamma_ifgo[j]          + beta_ifgo[j];
        float fg = (val[1][e] - m1) * i1 * gamma_ifgo[HD + j]     + beta_ifgo[HD + j] + 1.0f;
        float gg = (val[2][e] - m2) * i2 * gamma_ifgo[2 * HD + j] + beta_ifgo[2 * HD + j];
        float og = (val[3][e] - m3) * i3 * gamma_ifgo[3 * HD + j] + beta_ifgo[3 * HD + j];
        float ncr = cprev[(size_t)b * HD + j] * sigmoidf_(fg) + sigmoidf_(ig) * tanhf(gg);
        nc[e] = ncr;
        ogate[e] = og;
        cs += ncr;
        cq += ncr * ncr;
    }

    #pragma unroll
    for (int off = 16; off; off >>= 1) {
        cs += __shfl_xor_sync(0xffffffffu, cs, off);
        cq += __shfl_xor_sync(0xffffffffu, cq, off);
    }
    __syncthreads();
    if (lane == 0) { red[warp][0] = cs; red[warp][1] = cq; }
    __syncthreads();
    __shared__ float meanc_s, invc_s;
    if (tid == 0) {
        float ts = 0.f, tq2 = 0.f;
        #pragma unroll
        for (int w = 0; w < 8; w++) { ts += red[w][0]; tq2 += red[w][1]; }
        float mean = ts * (1.f / HD);
        float var  = (tq2 - (float)HD * mean * mean) * (1.f / (HD - 1));
        var = fmaxf(var, 0.f);
        meanc_s = mean;
        invc_s  = 1.f / (sqrtf(var) + EPS);
    }
    __syncthreads();
    const float mc = meanc_s, ic = invc_s;

    #pragma unroll
    for (int e = 0; e < 4; e++) {
        const int j = tid + e * 256;
        float ncn = (nc[e] - mc) * ic * gamma_c[j] + beta_c[j];
        out_c[(size_t)b * HD + j] = ncn;
        out_h[(size_t)b * HD + j] = tanhf(ncn) * sigmoidf_(ogate[e]);
    }
}

extern "C" void kernel_launch(void* const* d_in, const int* in_sizes, int n_in,
                              void* d_out, int out_size)
{
    const float* x          = (const float*)d_in[0];
    const float* h          = (const float*)d_in[1];
    const float* c          = (const float*)d_in[2];
    const float* w_ih       = (const float*)d_in[3];
    const float* b_ih       = (const float*)d_in[4];
    const float* w_hh       = (const float*)d_in[5];
    const float* gamma_ifgo = (const float*)d_in[6];
    const float* beta_ifgo  = (const float*)d_in[7];
    const float* gamma_c    = (const float*)d_in[8];
    const float* beta_c     = (const float*)d_in[9];

    float* out_h = (float*)d_out;
    float* out_c = out_h + (size_t)MB * HD;

    cudaFuncSetAttribute(gemm_tf32_kernel,
                         cudaFuncAttributeMaxDynamicSharedMemorySize, SMEM_TOTAL);

    dim3 ggrid(NB / BN, MB / BM);   // 16 x 64
    gemm_tf32_kernel<<<ggrid, 256, SMEM_TOTAL>>>(x, h, w_ih, w_hh);
    ln_lstm_kernel<<<MB, 256>>>(c, b_ih, gamma_ifgo, beta_ifgo, gamma_c, beta_c, out_h, out_c);
}

// round 4
// speedup vs baseline: 1.5466x; 1.0123x over previous
#include <cuda_runtime.h>
#include <cstdint>

// Problem constants
#define MB   8192      // batch rows (M)
#define NB   4096      // 4*H (N)
#define KB   2048      // In + H (K, logical concat)
#define HD   1024

// GEMM tiling (legacy mma.sync tf32 + ldmatrix + cp.async)
#define BM   128
#define BN   256
#define BK   32        // 32 fp32 = 128 bytes per SMEM row (SW128 atom)
#define STAGES 4

#define A_BYTES     (BM * 128)                 // 16384
#define B_BYTES     (BN * 128)                 // 32768
#define STAGE_BYTES (A_BYTES + B_BYTES)        // 49152
#define SMEM_TOTAL  (STAGES * STAGE_BYTES)     // 196608

// 134 MB scratch for v = x@w_ih^T + h@w_hh^T
__device__ float g_v[(size_t)MB * NB];

// ---------------- helpers ----------------
__device__ __forceinline__ uint32_t smem_u32(const void* p) {
    uint32_t a;
    asm("{ .reg .u64 t; cvta.to.shared.u64 t, %1; cvt.u32.u64 %0, t; }" : "=r"(a) : "l"(p));
    return a;
}
__device__ __forceinline__ void cp16(uint32_t dst, const void* src) {
    asm volatile("cp.async.cg.shared.global [%0], [%1], 16;" :: "r"(dst), "l"(src));
}
#define CP_COMMIT() asm volatile("cp.async.commit_group;" ::: "memory")
#define CP_WAIT2()  asm volatile("cp.async.wait_group 2;" ::: "memory")

__device__ __forceinline__ void ldsm4(uint32_t* r, uint32_t a) {
    asm volatile("ldmatrix.sync.aligned.m8n8.x4.shared.b16 {%0,%1,%2,%3}, [%4];"
        : "=r"(r[0]), "=r"(r[1]), "=r"(r[2]), "=r"(r[3]) : "r"(a));
}
__device__ __forceinline__ void mma_tf32(float* d, const uint32_t* a, const uint32_t* b) {
    asm volatile(
        "mma.sync.aligned.m16n8k8.row.col.f32.tf32.tf32.f32 "
        "{%0,%1,%2,%3}, {%4,%5,%6,%7}, {%8,%9}, {%0,%1,%2,%3};"
        : "+f"(d[0]), "+f"(d[1]), "+f"(d[2]), "+f"(d[3])
        : "r"(a[0]), "r"(a[1]), "r"(a[2]), "r"(a[3]), "r"(b[0]), "r"(b[1]));
}
// SW128 swizzle on byte offset (row*128 + chunk*16)
__device__ __forceinline__ uint32_t swz(uint32_t o) { return o ^ ((o >> 3) & 0x70); }

// ---------------- GEMM ----------------
// grid (NB/BN=16, MB/BM=64), 256 threads = 8 warps, warp tile 64x64 (2x4 warp grid)
__global__ void __launch_bounds__(256, 1)
gemm_tf32_kernel(const float* __restrict__ x, const float* __restrict__ h,
                 const float* __restrict__ w_ih, const float* __restrict__ w_hh)
{
    extern __shared__ char smem[];
    const uint32_t sb = smem_u32(smem);
    const int tid = threadIdx.x, warp = tid >> 5, lane = tid & 31;
    const int bm = blockIdx.y * BM;
    const int bn = blockIdx.x * BN;
    const int wm = (warp & 1) * 64;
    const int wn = (warp >> 1) * 64;
    const int g  = lane >> 3, L = lane & 7;     // ldmatrix lane-group / row-in-group

    // issue one stage of cp.async loads (tile t -> slot t&3)
    auto issue = [&](int t) {
        const int s = t & 3;
        const float *As, *Bs;
        int kk;
        if (t < 32) { As = x; Bs = w_ih; kk = t * 32; }
        else        { As = h; Bs = w_hh; kk = t * 32 - 1024; }
        const uint32_t abase = sb + s * STAGE_BYTES;
        const uint32_t bbase = abase + A_BYTES;
        #pragma unroll
        for (int i = 0; i < 4; i++) {           // A: 128 rows x 8 chunks
            const int id = tid + 256 * i, r = id >> 3, c = id & 7;
            cp16(abase + swz((uint32_t)(r * 128 + c * 16)),
                 As + (size_t)(bm + r) * 1024 + kk + c * 4);
        }
        #pragma unroll
        for (int i = 0; i < 8; i++) {           // B: 256 rows x 8 chunks
            const int id = tid + 256 * i, r = id >> 3, c = id & 7;
            cp16(bbase + swz((uint32_t)(r * 128 + c * 16)),
                 Bs + (size_t)(bn + r) * 1024 + kk + c * 4);
        }
    };

    float acc[4][8][4];
    #pragma unroll
    for (int i = 0; i < 4; i++)
        #pragma unroll
        for (int j = 0; j < 8; j++)
            #pragma unroll
            for (int k = 0; k < 4; k++) acc[i][j][k] = 0.f;

    issue(0); CP_COMMIT();
    issue(1); CP_COMMIT();
    issue(2); CP_COMMIT();

    const int T = KB / BK;   // 64
    for (int t = 0; t < T; t++) {
        const int s = t & 3;
        CP_WAIT2();
        __syncthreads();
        // Issue next stage FIRST: barrier above guarantees every warp finished
        // reading slot (t+3)&3 == (t-1)&3 during iteration t-1, so overwriting
        // it now is safe, and the LSU work overlaps this iteration's MMAs.
        if (t + 3 < T) issue(t + 3);
        CP_COMMIT();    // unconditional: keeps wait_group accounting exact

        const uint32_t abase = sb + s * STAGE_BYTES;
        const uint32_t bbase = abase + A_BYTES;

        #pragma unroll
        for (int ks = 0; ks < 4; ks++) {        // 4 x k8 per BK=32
            uint32_t af[4][4], bf[4][4];
            #pragma unroll
            for (int mt = 0; mt < 4; mt++) {
                const int row = wm + mt * 16 + (g & 1) * 8 + L;
                const int ch  = 2 * ks + (g >> 1);
                ldsm4(af[mt], abase + swz((uint32_t)(row * 128 + ch * 16)));
            }
            #pragma unroll
            for (int p = 0; p < 4; p++) {
                const int row = wn + p * 16 + (g >> 1) * 8 + L;
                const int ch  = 2 * ks + (g & 1);
                ldsm4(bf[p], bbase + swz((uint32_t)(row * 128 + ch * 16)));
            }
            #pragma unroll
            for (int mt = 0; mt < 4; mt++)
                #pragma unroll
                for (int p = 0; p < 4; p++) {
                    mma_tf32(acc[mt][2 * p],     af[mt], &bf[p][0]);
                    mma_tf32(acc[mt][2 * p + 1], af[mt], &bf[p][2]);
                }
        }
    }

    // epilogue: thread (q,tq): c0,c1 at (row+q, col+2tq), c2,c3 at row+q+8
    const int q = lane >> 2, tq = lane & 3;
    #pragma unroll
    for (int mt = 0; mt < 4; mt++) {
        const int rg = bm + wm + mt * 16 + q;
        #pragma unroll
        for (int nt = 0; nt < 8; nt++) {
            const int cg = bn + wn + nt * 8 + 2 * tq;
            *reinterpret_cast<float2*>(&g_v[(size_t)rg * NB + cg]) =
                make_float2(acc[mt][nt][0], acc[mt][nt][1]);
            *reinterpret_cast<float2*>(&g_v[(size_t)(rg + 8) * NB + cg]) =
                make_float2(acc[mt][nt][2], acc[mt][nt][3]);
        }
    }
}

// ---------------- LayerNorm-LSTM pointwise kernel (float4) ----------------
__device__ __forceinline__ float sigmoidf_(float v) { return 1.f / (1.f + expf(-v)); }

__global__ __launch_bounds__(256)
void ln_lstm_kernel(const float* __restrict__ cprev,
                    const float* __restrict__ b_ih,
                    const float* __restrict__ gamma_ifgo, const float* __restrict__ beta_ifgo,
                    const float* __restrict__ gamma_c,    const float* __restrict__ beta_c,
                    float* __restrict__ out_h, float* __restrict__ out_c)
{
    const float EPS = 1e-6f;
    const int b   = blockIdx.x;
    const int tid = threadIdx.x;
    const int warp = tid >> 5, lane = tid & 31;

    const float4* vb4 = reinterpret_cast<const float4*>(g_v + (size_t)b * NB);
    const float4* bi4 = reinterpret_cast<const float4*>(b_ih);
    const float4* ga4 = reinterpret_cast<const float4*>(gamma_ifgo);
    const float4* be4 = reinterpret_cast<const float4*>(beta_ifgo);
    const float4* gc4 = reinterpret_cast<const float4*>(gamma_c);
    const float4* bc4 = reinterpret_cast<const float4*>(beta_c);
    const float4* cp4 = reinterpret_cast<const float4*>(cprev) + (size_t)b * 256;
    float4* oh4 = reinterpret_cast<float4*>(out_h) + (size_t)b * 256;
    float4* oc4 = reinterpret_cast<float4*>(out_c) + (size_t)b * 256;

    // each thread owns float4 #tid of each gate (256 float4 per gate)
    float4 val[4];
    float s[4], q[4];
    #pragma unroll
    for (int g = 0; g < 4; g++) {
        float4 v = vb4[g * 256 + tid];
        float4 bb = bi4[g * 256 + tid];
        v.x += bb.x; v.y += bb.y; v.z += bb.z; v.w += bb.w;
        val[g] = v;
        s[g] = v.x + v.y + v.z + v.w;
        q[g] = v.x * v.x + v.y * v.y + v.z * v.z + v.w * v.w;
    }

    __shared__ float red[8][8];
    __shared__ float mean_s[4], inv_s[4];

    #pragma unroll
    for (int g = 0; g < 4; g++)
        #pragma unroll
        for (int off = 16; off; off >>= 1) {
            s[g] += __shfl_xor_sync(0xffffffffu, s[g], off);
            q[g] += __shfl_xor_sync(0xffffffffu, q[g], off);
        }
    if (lane == 0) {
        #pragma unroll
        for (int g = 0; g < 4; g++) { red[warp][g] = s[g]; red[warp][g + 4] = q[g]; }
    }
    __syncthreads();
    if (tid < 4) {
        float ts = 0.f, tq2 = 0.f;
        #pragma unroll
        for (int w = 0; w < 8; w++) { ts += red[w][tid]; tq2 += red[w][tid + 4]; }
        float mean = ts * (1.f / HD);
        float var  = (tq2 - (float)HD * mean * mean) * (1.f / (HD - 1));
        var = fmaxf(var, 0.f);
        mean_s[tid] = mean;
        inv_s[tid]  = 1.f / (sqrtf(var) + EPS);
    }
    __syncthreads();

    float4 gam[4], bet[4];
    #pragma unroll
    for (int g = 0; g < 4; g++) { gam[g] = ga4[g * 256 + tid]; bet[g] = be4[g * 256 + tid]; }
    const float4 cpv = cp4[tid];

    float ivals[4], fvals[4], gvals[4], ovals[4];
    {
        const float m0 = mean_s[0], m1 = mean_s[1], m2 = mean_s[2], m3 = mean_s[3];
        const float i0 = inv_s[0],  i1 = inv_s[1],  i2 = inv_s[2],  i3 = inv_s[3];
        const float* v0 = &val[0].x; const float* v1 = &val[1].x;
        const float* v2 = &val[2].x; const float* v3 = &val[3].x;
        const float* g0 = &gam[0].x; const float* g1 = &gam[1].x;
        const float* g2 = &gam[2].x; const float* g3 = &gam[3].x;
        const float* b0 = &bet[0].x; const float* b1 = &bet[1].x;
        const float* b2 = &bet[2].x; const float* b3 = &bet[3].x;
        #pragma unroll
        for (int e = 0; e < 4; e++) {
            ivals[e] = (v0[e] - m0) * i0 * g0[e] + b0[e];
            fvals[e] = (v1[e] - m1) * i1 * g1[e] + b1[e] + 1.0f;
            gvals[e] = (v2[e] - m2) * i2 * g2[e] + b2[e];
            ovals[e] = (v3[e] - m3) * i3 * g3[e] + b3[e];
        }
    }

    float nc[4];
    float cs = 0.f, cq = 0.f;
    const float* cpe = &cpv.x;
    #pragma unroll
    for (int e = 0; e < 4; e++) {
        float ncr = cpe[e] * sigmoidf_(fvals[e]) + sigmoidf_(ivals[e]) * tanhf(gvals[e]);
        nc[e] = ncr;
        cs += ncr;
        cq += ncr * ncr;
    }

    #pragma unroll
    for (int off = 16; off; off >>= 1) {
        cs += __shfl_xor_sync(0xffffffffu, cs, off);
        cq += __shfl_xor_sync(0xffffffffu, cq, off);
    }
    __syncthreads();
    if (lane == 0) { red[warp][0] = cs; red[warp][1] = cq; }
    __syncthreads();
    __shared__ float meanc_s, invc_s;
    if (tid == 0) {
        float ts = 0.f, tq2 = 0.f;
        #pragma unroll
        for (int w = 0; w < 8; w++) { ts += red[w][0]; tq2 += red[w][1]; }
        float mean = ts * (1.f / HD);
        float var  = (tq2 - (float)HD * mean * mean) * (1.f / (HD - 1));
        var = fmaxf(var, 0.f);
        meanc_s = mean;
        invc_s  = 1.f / (sqrtf(var) + EPS);
    }
    __syncthreads();
    const float mc = meanc_s, ic = invc_s;

    const float4 gcv = gc4[tid], bcv = bc4[tid];
    const float* gce = &gcv.x; const float* bce = &bcv.x;
    float4 outc, outh;
    float* ocp = &outc.x; float* ohp = &outh.x;
    #pragma unroll
    for (int e = 0; e < 4; e++) {
        float ncn = (nc[e] - mc) * ic * gce[e] + bce[e];
        ocp[e] = ncn;
        ohp[e] = tanhf(ncn) * sigmoidf_(ovals[e]);
    }
    oc4[tid] = outc;
    oh4[tid] = outh;
}

extern "C" void kernel_launch(void* const* d_in, const int* in_sizes, int n_in,
                              void* d_out, int out_size)
{
    const float* x          = (const float*)d_in[0];
    const float* h          = (const float*)d_in[1];
    const float* c          = (const float*)d_in[2];
    const float* w_ih       = (const float*)d_in[3];
    const float* b_ih       = (const float*)d_in[4];
    const float* w_hh       = (const float*)d_in[5];
    const float* gamma_ifgo = (const float*)d_in[6];
    const float* beta_ifgo  = (const float*)d_in[7];
    const float* gamma_c    = (const float*)d_in[8];
    const float* beta_c     = (const float*)d_in[9];

    float* out_h = (float*)d_out;
    float* out_c = out_h + (size_t)MB * HD;

    cudaFuncSetAttribute(gemm_tf32_kernel,
                         cudaFuncAttributeMaxDynamicSharedMemorySize, SMEM_TOTAL);

    dim3 ggrid(NB / BN, MB / BM);   // 16 x 64
    gemm_tf32_kernel<<<ggrid, 256, SMEM_TOTAL>>>(x, h, w_ih, w_hh);
    ln_lstm_kernel<<<MB, 256>>>(c, b_ih, gamma_ifgo, beta_ifgo, gamma_c, beta_c, out_h, out_c);
}

// round 5
// speedup vs baseline: 1.6244x; 1.0503x over previous
#include <cuda_runtime.h>
#include <cstdint>

// Problem constants
#define MB   8192      // batch rows (M)
#define NB   4096      // 4*H (N)
#define KB   2048      // In + H (K, logical concat)
#define HD   1024

// GEMM tiling (legacy mma.sync tf32 + ldmatrix + cp.async)
#define BM   128
#define BN   256
#define BK   32        // 32 fp32 = 128 bytes per SMEM row (SW128 atom)
#define STAGES 4
#define NTHREADS 512   // 16 warps, warp grid 2(M) x 8(N), warptile 64x32

#define A_BYTES     (BM * 128)                 // 16384
#define B_BYTES     (BN * 128)                 // 32768
#define STAGE_BYTES (A_BYTES + B_BYTES)        // 49152
#define SMEM_TOTAL  (STAGES * STAGE_BYTES)     // 196608

// 134 MB scratch for v = x@w_ih^T + h@w_hh^T
__device__ float g_v[(size_t)MB * NB];

// ---------------- helpers ----------------
__device__ __forceinline__ uint32_t smem_u32(const void* p) {
    uint32_t a;
    asm("{ .reg .u64 t; cvta.to.shared.u64 t, %1; cvt.u32.u64 %0, t; }" : "=r"(a) : "l"(p));
    return a;
}
__device__ __forceinline__ void cp16(uint32_t dst, const void* src) {
    asm volatile("cp.async.cg.shared.global [%0], [%1], 16;" :: "r"(dst), "l"(src));
}
#define CP_COMMIT() asm volatile("cp.async.commit_group;" ::: "memory")
#define CP_WAIT2()  asm volatile("cp.async.wait_group 2;" ::: "memory")

__device__ __forceinline__ void ldsm4(uint32_t* r, uint32_t a) {
    asm volatile("ldmatrix.sync.aligned.m8n8.x4.shared.b16 {%0,%1,%2,%3}, [%4];"
        : "=r"(r[0]), "=r"(r[1]), "=r"(r[2]), "=r"(r[3]) : "r"(a));
}
__device__ __forceinline__ void mma_tf32(float* d, const uint32_t* a, const uint32_t* b) {
    asm volatile(
        "mma.sync.aligned.m16n8k8.row.col.f32.tf32.tf32.f32 "
        "{%0,%1,%2,%3}, {%4,%5,%6,%7}, {%8,%9}, {%0,%1,%2,%3};"
        : "+f"(d[0]), "+f"(d[1]), "+f"(d[2]), "+f"(d[3])
        : "r"(a[0]), "r"(a[1]), "r"(a[2]), "r"(a[3]), "r"(b[0]), "r"(b[1]));
}
// SW128 swizzle on byte offset (row*128 + chunk*16)
__device__ __forceinline__ uint32_t swz(uint32_t o) { return o ^ ((o >> 3) & 0x70); }

// ---------------- GEMM ----------------
// grid (NB/BN=16, MB/BM=64), 512 threads = 16 warps, warptile 64x32
__global__ void __launch_bounds__(NTHREADS, 1)
gemm_tf32_kernel(const float* __restrict__ x, const float* __restrict__ h,
                 const float* __restrict__ w_ih, const float* __restrict__ w_hh)
{
    extern __shared__ char smem[];
    const uint32_t sb = smem_u32(smem);
    const int tid = threadIdx.x, warp = tid >> 5, lane = tid & 31;
    const int bm = blockIdx.y * BM;
    const int bn = blockIdx.x * BN;
    const int wm = (warp & 1) * 64;       // 2 warp rows
    const int wn = (warp >> 1) * 32;      // 8 warp cols
    const int g  = lane >> 3, L = lane & 7;     // ldmatrix lane-group / row-in-group

    // issue one stage of cp.async loads (tile t -> slot t&3)
    auto issue = [&](int t) {
        const int s = t & 3;
        const float *As, *Bs;
        int kk;
        if (t < 32) { As = x; Bs = w_ih; kk = t * 32; }
        else        { As = h; Bs = w_hh; kk = t * 32 - 1024; }
        const uint32_t abase = sb + s * STAGE_BYTES;
        const uint32_t bbase = abase + A_BYTES;
        #pragma unroll
        for (int i = 0; i < 2; i++) {           // A: 128 rows x 8 chunks = 1024
            const int id = tid + NTHREADS * i, r = id >> 3, c = id & 7;
            cp16(abase + swz((uint32_t)(r * 128 + c * 16)),
                 As + (size_t)(bm + r) * 1024 + kk + c * 4);
        }
        #pragma unroll
        for (int i = 0; i < 4; i++) {           // B: 256 rows x 8 chunks = 2048
            const int id = tid + NTHREADS * i, r = id >> 3, c = id & 7;
            cp16(bbase + swz((uint32_t)(r * 128 + c * 16)),
                 Bs + (size_t)(bn + r) * 1024 + kk + c * 4);
        }
    };

    float acc[4][4][4];   // mt (4 x m16), nt (4 x n8), frag
    #pragma unroll
    for (int i = 0; i < 4; i++)
        #pragma unroll
        for (int j = 0; j < 4; j++)
            #pragma unroll
            for (int k = 0; k < 4; k++) acc[i][j][k] = 0.f;

    issue(0); CP_COMMIT();
    issue(1); CP_COMMIT();
    issue(2); CP_COMMIT();

    const int T = KB / BK;   // 64
    for (int t = 0; t < T; t++) {
        const int s = t & 3;
        CP_WAIT2();
        __syncthreads();
        // Issue next stage first: the barrier guarantees every warp finished
        // reading slot (t-1)&3 last iteration, so overwriting it is safe and
        // the LSU work overlaps this iteration's MMAs.
        if (t + 3 < T) issue(t + 3);
        CP_COMMIT();    // unconditional: keeps wait_group accounting exact

        const uint32_t abase = sb + s * STAGE_BYTES;
        const uint32_t bbase = abase + A_BYTES;

        #pragma unroll
        for (int ks = 0; ks < 4; ks++) {        // 4 x k8 per BK=32
            uint32_t af[4][4], bf[2][4];
            #pragma unroll
            for (int mt = 0; mt < 4; mt++) {    // A: rows wm..wm+63
                const int row = wm + mt * 16 + (g & 1) * 8 + L;
                const int ch  = 2 * ks + (g >> 1);
                ldsm4(af[mt], abase + swz((uint32_t)(row * 128 + ch * 16)));
            }
            #pragma unroll
            for (int p = 0; p < 2; p++) {       // B: rows wn..wn+31 (2 x n16)
                const int row = wn + p * 16 + (g >> 1) * 8 + L;
                const int ch  = 2 * ks + (g & 1);
                ldsm4(bf[p], bbase + swz((uint32_t)(row * 128 + ch * 16)));
            }
            #pragma unroll
            for (int mt = 0; mt < 4; mt++)
                #pragma unroll
                for (int p = 0; p < 2; p++) {
                    mma_tf32(acc[mt][2 * p],     af[mt], &bf[p][0]);
                    mma_tf32(acc[mt][2 * p + 1], af[mt], &bf[p][2]);
                }
        }
    }

    // epilogue: thread (q,tq): c0,c1 at (row+q, col+2tq), c2,c3 at row+q+8
    const int q = lane >> 2, tq = lane & 3;
    #pragma unroll
    for (int mt = 0; mt < 4; mt++) {
        const int rg = bm + wm + mt * 16 + q;
        #pragma unroll
        for (int nt = 0; nt < 4; nt++) {
            const int cg = bn + wn + nt * 8 + 2 * tq;
            *reinterpret_cast<float2*>(&g_v[(size_t)rg * NB + cg]) =
                make_float2(acc[mt][nt][0], acc[mt][nt][1]);
            *reinterpret_cast<float2*>(&g_v[(size_t)(rg + 8) * NB + cg]) =
                make_float2(acc[mt][nt][2], acc[mt][nt][3]);
        }
    }
}

// ---------------- LayerNorm-LSTM pointwise kernel (float4) ----------------
__device__ __forceinline__ float sigmoidf_(float v) { return 1.f / (1.f + expf(-v)); }

__global__ __launch_bounds__(256)
void ln_lstm_kernel(const float* __restrict__ cprev,
                    const float* __restrict__ b_ih,
                    const float* __restrict__ gamma_ifgo, const float* __restrict__ beta_ifgo,
                    const float* __restrict__ gamma_c,    const float* __restrict__ beta_c,
                    float* __restrict__ out_h, float* __restrict__ out_c)
{
    const float EPS = 1e-6f;
    const int b   = blockIdx.x;
    const int tid = threadIdx.x;
    const int warp = tid >> 5, lane = tid & 31;

    const float4* vb4 = reinterpret_cast<const float4*>(g_v + (size_t)b * NB);
    const float4* bi4 = reinterpret_cast<const float4*>(b_ih);
    const float4* ga4 = reinterpret_cast<const float4*>(gamma_ifgo);
    const float4* be4 = reinterpret_cast<const float4*>(beta_ifgo);
    const float4* gc4 = reinterpret_cast<const float4*>(gamma_c);
    const float4* bc4 = reinterpret_cast<const float4*>(beta_c);
    const float4* cp4 = reinterpret_cast<const float4*>(cprev) + (size_t)b * 256;
    float4* oh4 = reinterpret_cast<float4*>(out_h) + (size_t)b * 256;
    float4* oc4 = reinterpret_cast<float4*>(out_c) + (size_t)b * 256;

    float4 val[4];
    float s[4], q[4];
    #pragma unroll
    for (int g = 0; g < 4; g++) {
        float4 v = vb4[g * 256 + tid];
        float4 bb = bi4[g * 256 + tid];
        v.x += bb.x; v.y += bb.y; v.z += bb.z; v.w += bb.w;
        val[g] = v;
        s[g] = v.x + v.y + v.z + v.w;
        q[g] = v.x * v.x + v.y * v.y + v.z * v.z + v.w * v.w;
    }

    __shared__ float red[8][8];
    __shared__ float mean_s[4], inv_s[4];

    #pragma unroll
    for (int g = 0; g < 4; g++)
        #pragma unroll
        for (int off = 16; off; off >>= 1) {
            s[g] += __shfl_xor_sync(0xffffffffu, s[g], off);
            q[g] += __shfl_xor_sync(0xffffffffu, q[g], off);
        }
    if (lane == 0) {
        #pragma unroll
        for (int g = 0; g < 4; g++) { red[warp][g] = s[g]; red[warp][g + 4] = q[g]; }
    }
    __syncthreads();
    if (tid < 4) {
        float ts = 0.f, tq2 = 0.f;
        #pragma unroll
        for (int w = 0; w < 8; w++) { ts += red[w][tid]; tq2 += red[w][tid + 4]; }
        float mean = ts * (1.f / HD);
        float var  = (tq2 - (float)HD * mean * mean) * (1.f / (HD - 1));
        var = fmaxf(var, 0.f);
        mean_s[tid] = mean;
        inv_s[tid]  = 1.f / (sqrtf(var) + EPS);
    }
    __syncthreads();

    float4 gam[4], bet[4];
    #pragma unroll
    for (int g = 0; g < 4; g++) { gam[g] = ga4[g * 256 + tid]; bet[g] = be4[g * 256 + tid]; }
    const float4 cpv = cp4[tid];

    float ivals[4], fvals[4], gvals[4], ovals[4];
    {
        const float m0 = mean_s[0], m1 = mean_s[1], m2 = mean_s[2], m3 = mean_s[3];
        const float i0 = inv_s[0],  i1 = inv_s[1],  i2 = inv_s[2],  i3 = inv_s[3];
        const float* v0 = &val[0].x; const float* v1 = &val[1].x;
        const float* v2 = &val[2].x; const float* v3 = &val[3].x;
        const float* g0 = &gam[0].x; const float* g1 = &gam[1].x;
        const float* g2 = &gam[2].x; const float* g3 = &gam[3].x;
        const float* b0 = &bet[0].x; const float* b1 = &bet[1].x;
        const float* b2 = &bet[2].x; const float* b3 = &bet[3].x;
        #pragma unroll
        for (int e = 0; e < 4; e++) {
            ivals[e] = (v0[e] - m0) * i0 * g0[e] + b0[e];
            fvals[e] = (v1[e] - m1) * i1 * g1[e] + b1[e] + 1.0f;
            gvals[e] = (v2[e] - m2) * i2 * g2[e] + b2[e];
            ovals[e] = (v3[e] - m3) * i3 * g3[e] + b3[e];
        }
    }

    float nc[4];
    float cs = 0.f, cq = 0.f;
    const float* cpe = &cpv.x;
    #pragma unroll
    for (int e = 0; e < 4; e++) {
        float ncr = cpe[e] * sigmoidf_(fvals[e]) + sigmoidf_(ivals[e]) * tanhf(gvals[e]);
        nc[e] = ncr;
        cs += ncr;
        cq += ncr * ncr;
    }

    #pragma unroll
    for (int off = 16; off; off >>= 1) {
        cs += __shfl_xor_sync(0xffffffffu, cs, off);
        cq += __shfl_xor_sync(0xffffffffu, cq, off);
    }
    __syncthreads();
    if (lane == 0) { red[warp][0] = cs; red[warp][1] = cq; }
    __syncthreads();
    __shared__ float meanc_s, invc_s;
    if (tid == 0) {
        float ts = 0.f, tq2 = 0.f;
        #pragma unroll
        for (int w = 0; w < 8; w++) { ts += red[w][0]; tq2 += red[w][1]; }
        float mean = ts * (1.f / HD);
        float var  = (tq2 - (float)HD * mean * mean) * (1.f / (HD - 1));
        var = fmaxf(var, 0.f);
        meanc_s = mean;
        invc_s  = 1.f / (sqrtf(var) + EPS);
    }
    __syncthreads();
    const float mc = meanc_s, ic = invc_s;

    const float4 gcv = gc4[tid], bcv = bc4[tid];
    const float* gce = &gcv.x; const float* bce = &bcv.x;
    float4 outc, outh;
    float* ocp = &outc.x; float* ohp = &outh.x;
    #pragma unroll
    for (int e = 0; e < 4; e++) {
        float ncn = (nc[e] - mc) * ic * gce[e] + bce[e];
        ocp[e] = ncn;
        ohp[e] = tanhf(ncn) * sigmoidf_(ovals[e]);
    }
    oc4[tid] = outc;
    oh4[tid] = outh;
}

extern "C" void kernel_launch(void* const* d_in, const int* in_sizes, int n_in,
                              void* d_out, int out_size)
{
    const float* x          = (const float*)d_in[0];
    const float* h          = (const float*)d_in[1];
    const float* c          = (const float*)d_in[2];
    const float* w_ih       = (const float*)d_in[3];
    const float* b_ih       = (const float*)d_in[4];
    const float* w_hh       = (const float*)d_in[5];
    const float* gamma_ifgo = (const float*)d_in[6];
    const float* beta_ifgo  = (const float*)d_in[7];
    const float* gamma_c    = (const float*)d_in[8];
    const float* beta_c     = (const float*)d_in[9];

    float* out_h = (float*)d_out;
    float* out_c = out_h + (size_t)MB * HD;

    cudaFuncSetAttribute(gemm_tf32_kernel,
                         cudaFuncAttributeMaxDynamicSharedMemorySize, SMEM_TOTAL);

    dim3 ggrid(NB / BN, MB / BM);   // 16 x 64
    gemm_tf32_kernel<<<ggrid, NTHREADS, SMEM_TOTAL>>>(x, h, w_ih, w_hh);
    ln_lstm_kernel<<<MB, 256>>>(c, b_ih, gamma_ifgo, beta_ifgo, gamma_c, beta_c, out_h, out_c);
}

// round 6
// speedup vs baseline: 2.6548x; 1.6343x over previous
#include <cuda_runtime.h>
#include <cuda_fp16.h>
#include <cstdint>

// Problem constants
#define MB   8192      // batch rows (M)
#define NB   4096      // 4*H (N)
#define KB   2048      // In + H (K, logical concat)
#define HD   1024

// GEMM tiling (fp16 mma.sync m16n8k16 + ldmatrix + cp.async)
#define BM   128
#define BN   256
#define BK   64        // 64 fp16 = 128 bytes per SMEM row (SW128 atom)
#define STAGES 4
#define NTHREADS 512   // 16 warps, warp grid 2(M) x 8(N), warptile 64x32

#define A_BYTES     (BM * 128)                 // 16384
#define B_BYTES     (BN * 128)                 // 32768
#define STAGE_BYTES (A_BYTES + B_BYTES)        // 49152
#define SMEM_TOTAL  (STAGES * STAGE_BYTES)     // 196608

// scratch: fp32 pre-activations + fp16 copies of inputs/weights
__device__ float g_v[(size_t)MB * NB];                 // 134 MB
__device__ __half g_x16[(size_t)MB * 1024];            // 16 MB
__device__ __half g_h16[(size_t)MB * 1024];            // 16 MB
__device__ __half g_wih16[(size_t)NB * 1024];          // 8 MB
__device__ __half g_whh16[(size_t)NB * 1024];          // 8 MB

// ---------------- helpers ----------------
__device__ __forceinline__ uint32_t smem_u32(const void* p) {
    uint32_t a;
    asm("{ .reg .u64 t; cvta.to.shared.u64 t, %1; cvt.u32.u64 %0, t; }" : "=r"(a) : "l"(p));
    return a;
}
__device__ __forceinline__ void cp16(uint32_t dst, const void* src) {
    asm volatile("cp.async.cg.shared.global [%0], [%1], 16;" :: "r"(dst), "l"(src));
}
#define CP_COMMIT() asm volatile("cp.async.commit_group;" ::: "memory")
#define CP_WAIT2()  asm volatile("cp.async.wait_group 2;" ::: "memory")

__device__ __forceinline__ void ldsm4(uint32_t* r, uint32_t a) {
    asm volatile("ldmatrix.sync.aligned.m8n8.x4.shared.b16 {%0,%1,%2,%3}, [%4];"
        : "=r"(r[0]), "=r"(r[1]), "=r"(r[2]), "=r"(r[3]) : "r"(a));
}
__device__ __forceinline__ void mma_f16(float* d, const uint32_t* a, const uint32_t* b) {
    asm volatile(
        "mma.sync.aligned.m16n8k16.row.col.f32.f16.f16.f32 "
        "{%0,%1,%2,%3}, {%4,%5,%6,%7}, {%8,%9}, {%0,%1,%2,%3};"
        : "+f"(d[0]), "+f"(d[1]), "+f"(d[2]), "+f"(d[3])
        : "r"(a[0]), "r"(a[1]), "r"(a[2]), "r"(a[3]), "r"(b[0]), "r"(b[1]));
}
// SW128 swizzle on byte offset (row*128 + chunk*16)
__device__ __forceinline__ uint32_t swz(uint32_t o) { return o ^ ((o >> 3) & 0x70); }

// ---------------- fp32 -> fp16 conversion pre-pass ----------------
__global__ void __launch_bounds__(512)
cvt_kernel(const float4* __restrict__ src, uint2* __restrict__ dst, int n4)
{
    const int stride = gridDim.x * blockDim.x;
    for (int i = blockIdx.x * blockDim.x + threadIdx.x; i < n4; i += stride) {
        float4 f = src[i];
        __half2 h01 = __floats2half2_rn(f.x, f.y);
        __half2 h23 = __floats2half2_rn(f.z, f.w);
        uint2 o;
        o.x = *reinterpret_cast<uint32_t*>(&h01);
        o.y = *reinterpret_cast<uint32_t*>(&h23);
        dst[i] = o;
    }
}

// ---------------- GEMM ----------------
// grid (NB/BN=16, MB/BM=64), 512 threads = 16 warps, warptile 64x32
__global__ void __launch_bounds__(NTHREADS, 1)
gemm_f16_kernel()
{
    extern __shared__ char smem[];
    const uint32_t sb = smem_u32(smem);
    const int tid = threadIdx.x, warp = tid >> 5, lane = tid & 31;
    const int bm = blockIdx.y * BM;
    const int bn = blockIdx.x * BN;
    const int wm = (warp & 1) * 64;       // 2 warp rows
    const int wn = (warp >> 1) * 32;      // 8 warp cols
    const int g  = lane >> 3, L = lane & 7;     // ldmatrix lane-group / row-in-group

    // issue one stage of cp.async loads (tile t -> slot t&3)
    auto issue = [&](int t) {
        const int s = t & 3;
        const __half *As, *Bs;
        int kk;
        if (t < 16) { As = g_x16; Bs = g_wih16; kk = t * BK; }
        else        { As = g_h16; Bs = g_whh16; kk = t * BK - 1024; }
        const uint32_t abase = sb + s * STAGE_BYTES;
        const uint32_t bbase = abase + A_BYTES;
        #pragma unroll
        for (int i = 0; i < 2; i++) {           // A: 128 rows x 8 chunks = 1024
            const int id = tid + NTHREADS * i, r = id >> 3, c = id & 7;
            cp16(abase + swz((uint32_t)(r * 128 + c * 16)),
                 As + (size_t)(bm + r) * 1024 + kk + c * 8);
        }
        #pragma unroll
        for (int i = 0; i < 4; i++) {           // B: 256 rows x 8 chunks = 2048
            const int id = tid + NTHREADS * i, r = id >> 3, c = id & 7;
            cp16(bbase + swz((uint32_t)(r * 128 + c * 16)),
                 Bs + (size_t)(bn + r) * 1024 + kk + c * 8);
        }
    };

    float acc[4][4][4];   // mt (4 x m16), nt (4 x n8), frag
    #pragma unroll
    for (int i = 0; i < 4; i++)
        #pragma unroll
        for (int j = 0; j < 4; j++)
            #pragma unroll
            for (int k = 0; k < 4; k++) acc[i][j][k] = 0.f;

    issue(0); CP_COMMIT();
    issue(1); CP_COMMIT();
    issue(2); CP_COMMIT();

    const int T = KB / BK;   // 32
    for (int t = 0; t < T; t++) {
        const int s = t & 3;
        CP_WAIT2();
        __syncthreads();
        // Issue next stage first: the barrier guarantees every warp finished
        // reading slot (t-1)&3 last iteration, so overwriting it is safe and
        // the LSU work overlaps this iteration's MMAs.
        if (t + 3 < T) issue(t + 3);
        CP_COMMIT();    // unconditional: keeps wait_group accounting exact

        const uint32_t abase = sb + s * STAGE_BYTES;
        const uint32_t bbase = abase + A_BYTES;

        #pragma unroll
        for (int ks = 0; ks < 4; ks++) {        // 4 x k16 per BK=64
            uint32_t af[4][4], bf[2][4];
            // A 16x16 frags: mat g -> row wm+mt*16+(g&1)*8+L, 16B chunk 2ks+(g>>1)
            #pragma unroll
            for (int mt = 0; mt < 4; mt++) {
                const int row = wm + mt * 16 + (g & 1) * 8 + L;
                const int ch  = 2 * ks + (g >> 1);
                ldsm4(af[mt], abase + swz((uint32_t)(row * 128 + ch * 16)));
            }
            // B n16xk16 frags: mat g -> row wn+p*16+(g>>1)*8+L, chunk 2ks+(g&1)
            // regs: r0=n(0-7)k(0-7), r1=n(0-7)k(8-15), r2=n(8-15)k(0-7), r3=n(8-15)k(8-15)
            #pragma unroll
            for (int p = 0; p < 2; p++) {
                const int row = wn + p * 16 + (g >> 1) * 8 + L;
                const int ch  = 2 * ks + (g & 1);
                ldsm4(bf[p], bbase + swz((uint32_t)(row * 128 + ch * 16)));
            }
            #pragma unroll
            for (int mt = 0; mt < 4; mt++)
                #pragma unroll
                for (int p = 0; p < 2; p++) {
                    mma_f16(acc[mt][2 * p],     af[mt], &bf[p][0]);   // n8 lo: {r0,r1}
                    mma_f16(acc[mt][2 * p + 1], af[mt], &bf[p][2]);   // n8 hi: {r2,r3}
                }
        }
    }

    // epilogue: thread (q,tq): c0,c1 at (row+q, col+2tq), c2,c3 at row+q+8
    const int q = lane >> 2, tq = lane & 3;
    #pragma unroll
    for (int mt = 0; mt < 4; mt++) {
        const int rg = bm + wm + mt * 16 + q;
        #pragma unroll
        for (int nt = 0; nt < 4; nt++) {
            const int cg = bn + wn + nt * 8 + 2 * tq;
            *reinterpret_cast<float2*>(&g_v[(size_t)rg * NB + cg]) =
                make_float2(acc[mt][nt][0], acc[mt][nt][1]);
            *reinterpret_cast<float2*>(&g_v[(size_t)(rg + 8) * NB + cg]) =
                make_float2(acc[mt][nt][2], acc[mt][nt][3]);
        }
    }
}

// ---------------- LayerNorm-LSTM pointwise kernel (float4) ----------------
__device__ __forceinline__ float sigmoidf_(float v) { return 1.f / (1.f + expf(-v)); }

__global__ __launch_bounds__(256)
void ln_lstm_kernel(const float* __restrict__ cprev,
                    const float* __restrict__ b_ih,
                    const float* __restrict__ gamma_ifgo, const float* __restrict__ beta_ifgo,
                    const float* __restrict__ gamma_c,    const float* __restrict__ beta_c,
                    float* __restrict__ out_h, float* __restrict__ out_c)
{
    const float EPS = 1e-6f;
    const int b   = blockIdx.x;
    const int tid = threadIdx.x;
    const int warp = tid >> 5, lane = tid & 31;

    const float4* vb4 = reinterpret_cast<const float4*>(g_v + (size_t)b * NB);
    const float4* bi4 = reinterpret_cast<const float4*>(b_ih);
    const float4* ga4 = reinterpret_cast<const float4*>(gamma_ifgo);
    const float4* be4 = reinterpret_cast<const float4*>(beta_ifgo);
    const float4* gc4 = reinterpret_cast<const float4*>(gamma_c);
    const float4* bc4 = reinterpret_cast<const float4*>(beta_c);
    const float4* cp4 = reinterpret_cast<const float4*>(cprev) + (size_t)b * 256;
    float4* oh4 = reinterpret_cast<float4*>(out_h) + (size_t)b * 256;
    float4* oc4 = reinterpret_cast<float4*>(out_c) + (size_t)b * 256;

    float4 val[4];
    float s[4], q[4];
    #pragma unroll
    for (int g = 0; g < 4; g++) {
        float4 v = vb4[g * 256 + tid];
        float4 bb = bi4[g * 256 + tid];
        v.x += bb.x; v.y += bb.y; v.z += bb.z; v.w += bb.w;
        val[g] = v;
        s[g] = v.x + v.y + v.z + v.w;
        q[g] = v.x * v.x + v.y * v.y + v.z * v.z + v.w * v.w;
    }

    __shared__ float red[8][8];
    __shared__ float mean_s[4], inv_s[4];

    #pragma unroll
    for (int g = 0; g < 4; g++)
        #pragma unroll
        for (int off = 16; off; off >>= 1) {
            s[g] += __shfl_xor_sync(0xffffffffu, s[g], off);
            q[g] += __shfl_xor_sync(0xffffffffu, q[g], off);
        }
    if (lane == 0) {
        #pragma unroll
        for (int g = 0; g < 4; g++) { red[warp][g] = s[g]; red[warp][g + 4] = q[g]; }
    }
    __syncthreads();
    if (tid < 4) {
        float ts = 0.f, tq2 = 0.f;
        #pragma unroll
        for (int w = 0; w < 8; w++) { ts += red[w][tid]; tq2 += red[w][tid + 4]; }
        float mean = ts * (1.f / HD);
        float var  = (tq2 - (float)HD * mean * mean) * (1.f / (HD - 1));
        var = fmaxf(var, 0.f);
        mean_s[tid] = mean;
        inv_s[tid]  = 1.f / (sqrtf(var) + EPS);
    }
    __syncthreads();

    float4 gam[4], bet[4];
    #pragma unroll
    for (int g = 0; g < 4; g++) { gam[g] = ga4[g * 256 + tid]; bet[g] = be4[g * 256 + tid]; }
    const float4 cpv = cp4[tid];

    float ivals[4], fvals[4], gvals[4], ovals[4];
    {
        const float m0 = mean_s[0], m1 = mean_s[1], m2 = mean_s[2], m3 = mean_s[3];
        const float i0 = inv_s[0],  i1 = inv_s[1],  i2 = inv_s[2],  i3 = inv_s[3];
        const float* v0 = &val[0].x; const float* v1 = &val[1].x;
        const float* v2 = &val[2].x; const float* v3 = &val[3].x;
        const float* g0 = &gam[0].x; const float* g1 = &gam[1].x;
        const float* g2 = &gam[2].x; const float* g3 = &gam[3].x;
        const float* b0 = &bet[0].x; const float* b1 = &bet[1].x;
        const float* b2 = &bet[2].x; const float* b3 = &bet[3].x;
        #pragma unroll
        for (int e = 0; e < 4; e++) {
            ivals[e] = (v0[e] - m0) * i0 * g0[e] + b0[e];
            fvals[e] = (v1[e] - m1) * i1 * g1[e] + b1[e] + 1.0f;
            gvals[e] = (v2[e] - m2) * i2 * g2[e] + b2[e];
            ovals[e] = (v3[e] - m3) * i3 * g3[e] + b3[e];
        }
    }

    float nc[4];
    float cs = 0.f, cq = 0.f;
    const float* cpe = &cpv.x;
    #pragma unroll
    for (int e = 0; e < 4; e++) {
        float ncr = cpe[e] * sigmoidf_(fvals[e]) + sigmoidf_(ivals[e]) * tanhf(gvals[e]);
        nc[e] = ncr;
        cs += ncr;
        cq += ncr * ncr;
    }

    #pragma unroll
    for (int off = 16; off; off >>= 1) {
        cs += __shfl_xor_sync(0xffffffffu, cs, off);
        cq += __shfl_xor_sync(0xffffffffu, cq, off);
    }
    __syncthreads();
    if (lane == 0) { red[warp][0] = cs; red[warp][1] = cq; }
    __syncthreads();
    __shared__ float meanc_s, invc_s;
    if (tid == 0) {
        float ts = 0.f, tq2 = 0.f;
        #pragma unroll
        for (int w = 0; w < 8; w++) { ts += red[w][0]; tq2 += red[w][1]; }
        float mean = ts * (1.f / HD);
        float var  = (tq2 - (float)HD * mean * mean) * (1.f / (HD - 1));
        var = fmaxf(var, 0.f);
        meanc_s = mean;
        invc_s  = 1.f / (sqrtf(var) + EPS);
    }
    __syncthreads();
    const float mc = meanc_s, ic = invc_s;

    const float4 gcv = gc4[tid], bcv = bc4[tid];
    const float* gce = &gcv.x; const float* bce = &bcv.x;
    float4 outc, outh;
    float* ocp = &outc.x; float* ohp = &outh.x;
    #pragma unroll
    for (int e = 0; e < 4; e++) {
        float ncn = (nc[e] - mc) * ic * gce[e] + bce[e];
        ocp[e] = ncn;
        ohp[e] = tanhf(ncn) * sigmoidf_(ovals[e]);
    }
    oc4[tid] = outc;
    oh4[tid] = outh;
}

extern "C" void kernel_launch(void* const* d_in, const int* in_sizes, int n_in,
                              void* d_out, int out_size)
{
    const float* x          = (const float*)d_in[0];
    const float* h          = (const float*)d_in[1];
    const float* c          = (const float*)d_in[2];
    const float* w_ih       = (const float*)d_in[3];
    const float* b_ih       = (const float*)d_in[4];
    const float* w_hh       = (const float*)d_in[5];
    const float* gamma_ifgo = (const float*)d_in[6];
    const float* beta_ifgo  = (const float*)d_in[7];
    const float* gamma_c    = (const float*)d_in[8];
    const float* beta_c     = (const float*)d_in[9];

    float* out_h = (float*)d_out;
    float* out_c = out_h + (size_t)MB * HD;

    cudaFuncSetAttribute(gemm_f16_kernel,
                         cudaFuncAttributeMaxDynamicSharedMemorySize, SMEM_TOTAL);

    // resolve device scratch addresses (host-side; graph-capturable)
    void *px, *ph, *pwih, *pwhh;
    cudaGetSymbolAddress(&px,   g_x16);
    cudaGetSymbolAddress(&ph,   g_h16);
    cudaGetSymbolAddress(&pwih, g_wih16);
    cudaGetSymbolAddress(&pwhh, g_whh16);

    const int n4_xh = (MB * 1024) / 4;   // 2,097,152 float4
    const int n4_w  = (NB * 1024) / 4;   // 1,048,576 float4
    cvt_kernel<<<1024, 512>>>((const float4*)x,    (uint2*)px,   n4_xh);
    cvt_kernel<<<1024, 512>>>((const float4*)h,    (uint2*)ph,   n4_xh);
    cvt_kernel<<<1024, 512>>>((const float4*)w_ih, (uint2*)pwih, n4_w);
    cvt_kernel<<<1024, 512>>>((const float4*)w_hh, (uint2*)pwhh, n4_w);

    dim3 ggrid(NB / BN, MB / BM);   // 16 x 64
    gemm_f16_kernel<<<ggrid, NTHREADS, SMEM_TOTAL>>>();
    ln_lstm_kernel<<<MB, 256>>>(c, b_ih, gamma_ifgo, beta_ifgo, gamma_c, beta_c, out_h, out_c);
}